// round 13
// baseline (speedup 1.0000x reference)
#include <cuda_runtime.h>
#include <cuda_bf16.h>
#include <math.h>
#include <stdint.h>

// Problem constants
#define B_ROWS   2048
#define DDIM     128
#define NFEAT    100000
#define NSPLIT   18
#define NTILE    782            // ceil(100000/128)
#define NFPAD    (NTILE * 128)  // 100096
#define MGRPS    8              // 8 * 256 = 2048 rows
#define COEF     28.85390081777927f

#define NORM_BLKS 1024                        // 2 rows per block
#define CVT_BLKS  ((NFPAD * DDIM) / (256 * 8))  // 6256

// Scratch (device globals; no allocation allowed)
__device__ float          g_inorm[B_ROWS * DDIM];
__device__ __nv_bfloat16  g_abf[B_ROWS * DDIM];
__device__ __nv_bfloat16  g_fbf[NFPAD * DDIM];
__device__ float          g_partial[NSPLIT * B_ROWS];
__device__ float          g_loss[B_ROWS];

__device__ __forceinline__ float ex2f(float x) {
    float y; asm("ex2.approx.f32 %0, %1;" : "=f"(y) : "f"(x)); return y;
}
__device__ __forceinline__ uint32_t smem_u32(const void* p) {
    uint32_t a;
    asm("{ .reg .u64 t; cvta.to.shared.u64 t, %1; cvt.u32.u64 %0, t; }" : "=r"(a) : "l"(p));
    return a;
}
#define LDSM4(r, addr) \
    asm volatile("ldmatrix.sync.aligned.m8n8.x4.shared.b16 {%0,%1,%2,%3}, [%4];" \
        : "=r"((r)[0]), "=r"((r)[1]), "=r"((r)[2]), "=r"((r)[3]) : "r"(addr))
#define MMA16816(c, a, b0, b1) \
    asm volatile("mma.sync.aligned.m16n8k16.row.col.f32.bf16.bf16.f32 " \
        "{%0,%1,%2,%3},{%4,%5,%6,%7},{%8,%9},{%0,%1,%2,%3};" \
        : "+f"((c)[0]), "+f"((c)[1]), "+f"((c)[2]), "+f"((c)[3]) \
        : "r"((a)[0]), "r"((a)[1]), "r"((a)[2]), "r"((a)[3]), "r"(b0), "r"(b1))
#define CP_ASYNC16(dst, src) \
    asm volatile("cp.async.cg.shared.global [%0], [%1], 16;" :: "r"(dst), "l"(src))
#define CP_COMMIT() asm volatile("cp.async.commit_group;" ::: "memory")
#define CP_WAIT0()  asm volatile("cp.async.wait_group 0;" ::: "memory")

// int dtype handling (proven in R5)
__device__ __forceinline__ long long load_index(const void* p, int i, int is64) {
    if (is64) return ((const long long*)p)[i];
    return (long long)((const int*)p)[i];
}
__device__ __forceinline__ int sniff_is64(const void* p, int nelem) {
    const int* w = (const int*)p;
    int half = nelem / 2, stride = half / 32, allzero = 1;
    #pragma unroll
    for (int i = 0; i < 32; i++) if (w[2 * (i * stride) + 1] != 0) allzero = 0;
    return allzero;
}

// ---------------------------------------------------------------------------
// Kernel 1 (fused): blocks [0, NORM_BLKS) normalize input rows (2 rows/block);
// blocks [NORM_BLKS, NORM_BLKS+CVT_BLKS) convert features fp32->bf16 (padded).
// ---------------------------------------------------------------------------
__global__ void kprep(const float* __restrict__ in, const float* __restrict__ feats) {
    int tid = threadIdx.x;
    if (blockIdx.x < NORM_BLKS) {
        __shared__ float ws[2][4];
        int half = tid >> 7;                      // which of the 2 rows
        int t = tid & 127;
        int row = blockIdx.x * 2 + half;
        float v = in[row * DDIM + t];
        float ss = v * v;
        #pragma unroll
        for (int o = 16; o; o >>= 1) ss += __shfl_xor_sync(0xffffffffu, ss, o);
        if ((t & 31) == 0) ws[half][t >> 5] = ss;
        __syncthreads();
        float inv = 1.0f / fmaxf(sqrtf(ws[half][0] + ws[half][1] + ws[half][2] + ws[half][3]), 1e-12f);
        float nv = v * inv;
        g_inorm[row * DDIM + t] = nv;
        g_abf[row * DDIM + t] = __float2bfloat16_rn(nv);
    } else {
        long long base = ((long long)(blockIdx.x - NORM_BLKS) * 256 + tid) * 8;
        __nv_bfloat162 o[4];
        if (base < (long long)NFEAT * DDIM) {
            float4 v0 = *(const float4*)(feats + base);
            float4 v1 = *(const float4*)(feats + base + 4);
            o[0] = __floats2bfloat162_rn(v0.x, v0.y);
            o[1] = __floats2bfloat162_rn(v0.z, v0.w);
            o[2] = __floats2bfloat162_rn(v1.x, v1.y);
            o[3] = __floats2bfloat162_rn(v1.z, v1.w);
        } else {
            o[0] = o[1] = o[2] = o[3] = __floats2bfloat162_rn(0.f, 0.f);
        }
        *(uint4*)(g_fbf + base) = *(uint4*)o;
    }
}

// ---------------------------------------------------------------------------
// Kernel 2: bf16 mma.sync GEMM + exp-sum epilogue.
// Grid (NSPLIT, MGRPS), 512 threads (16 warps, 4M x 4N warp grid).
// CTA tile M=256, N=128, K=128. A resident (64KB); B double-buffered via
// cp.async (2x32KB). Barrier sits BEFORE the epilogue so warps drift:
// one warp's MUFU epilogue overlaps other warps' next-tile HMMAs.
// ---------------------------------------------------------------------------
__global__ void __launch_bounds__(512, 1)
kmma() {
    extern __shared__ char smem[];
    const int SA = 0, SB = 65536, SR = 131072;   // A 64K | B 2x32K | red 4K
    uint32_t sb = smem_u32(smem);
    int tid = threadIdx.x, wid = tid >> 5, lane = tid & 31;
    int warpM = wid >> 2, warpN = wid & 3;
    int split = blockIdx.x, mgrp = blockIdx.y;

    // B cp.async addressing: 4 chunks/thread/tile
    const char* gsrc[4]; uint32_t sdst[4];
    #pragma unroll
    for (int i = 0; i < 4; i++) {
        int ch = i * 512 + tid;
        int r = ch >> 4, c = ch & 15;
        gsrc[i] = (const char*)(g_fbf + ((size_t)(split * 128 + r)) * DDIM + c * 8);
        sdst[i] = sb + SB + r * 256 + ((c ^ (r & 7)) << 4);
    }
    const size_t gstep = (size_t)NSPLIT * 128 * DDIM * sizeof(__nv_bfloat16);

    // Issue B tile 0 -> buf 0 (in flight during A load)
    #pragma unroll
    for (int i = 0; i < 4; i++) CP_ASYNC16(sdst[i], gsrc[i]);
    CP_COMMIT();
    #pragma unroll
    for (int i = 0; i < 4; i++) gsrc[i] += gstep;

    // Load A tile: 256 rows x 16 chunks (swizzled), 8 chunks/thread
    #pragma unroll
    for (int i = 0; i < 8; i++) {
        int ch = i * 512 + tid;
        int r = ch >> 4, c = ch & 15;
        uint4 v = *(const uint4*)(g_abf + ((size_t)(mgrp * 256 + r)) * DDIM + c * 8);
        *(uint4*)(smem + SA + r * 256 + ((c ^ (r & 7)) << 4)) = v;
    }
    CP_WAIT0();
    __syncthreads();

    // ldmatrix per-thread address precompute
    int m_in16 = lane & 15, cselA = lane >> 4;
    uint32_t baseA[4]; int a7[4];
    #pragma unroll
    for (int mf = 0; mf < 4; mf++) {
        int row = warpM * 64 + mf * 16 + m_in16;
        baseA[mf] = sb + SA + row * 256;
        a7[mf] = row & 7;
    }
    int n_in16 = ((lane >> 4) << 3) | (lane & 7);
    int cselB = (lane >> 3) & 1;
    uint32_t baseB[2]; int b7[2];
    #pragma unroll
    for (int p = 0; p < 2; p++) {
        int row = warpN * 32 + p * 16 + n_in16;
        baseB[p] = sb + SB + row * 256;
        b7[p] = row & 7;
    }

    float rowsum[8];
    #pragma unroll
    for (int s = 0; s < 8; s++) rowsum[s] = 0.f;

    int j = 0;
    for (int t = split; t < NTILE; t += NSPLIT, j++) {
        int has_next = (t + NSPLIT < NTILE);
        // Issue next B tile into the other buffer (overlaps compute below)
        if (has_next) {
            uint32_t dx = (uint32_t)(((j + 1) & 1) * 32768);
            #pragma unroll
            for (int i = 0; i < 4; i++) CP_ASYNC16(sdst[i] + dx, gsrc[i]);
            CP_COMMIT();
            #pragma unroll
            for (int i = 0; i < 4; i++) gsrc[i] += gstep;
        }

        uint32_t bufoff = (uint32_t)((j & 1) * 32768);
        float acc[4][4][4];
        #pragma unroll
        for (int mf = 0; mf < 4; mf++)
            #pragma unroll
            for (int nf = 0; nf < 4; nf++)
                #pragma unroll
                for (int q = 0; q < 4; q++) acc[mf][nf][q] = 0.f;

        #pragma unroll
        for (int ks = 0; ks < 8; ks++) {
            uint32_t a[4][4], bb[2][4];
            #pragma unroll
            for (int mf = 0; mf < 4; mf++)
                LDSM4(a[mf], baseA[mf] + (((2 * ks + cselA) ^ a7[mf]) << 4));
            #pragma unroll
            for (int p = 0; p < 2; p++)
                LDSM4(bb[p], baseB[p] + bufoff + (((2 * ks + cselB) ^ b7[p]) << 4));
            #pragma unroll
            for (int mf = 0; mf < 4; mf++)
                #pragma unroll
                for (int nf = 0; nf < 4; nf++)
                    MMA16816(acc[mf][nf], a[mf], bb[nf >> 1][(nf & 1) * 2],
                             bb[nf >> 1][(nf & 1) * 2 + 1]);
        }

        // Barrier BEFORE epilogue: B-buf hazards close here; the register-only
        // epilogue below runs outside the protected region so warps overlap.
        if (has_next) CP_WAIT0();
        __syncthreads();

        // Epilogue: exp-sum into row accumulators (pad rows corrected in kpick)
        #pragma unroll
        for (int mf = 0; mf < 4; mf++)
            #pragma unroll
            for (int nf = 0; nf < 4; nf++)
                #pragma unroll
                for (int q = 0; q < 4; q++)
                    rowsum[mf * 2 + (q >> 1)] += ex2f(fmaf(acc[mf][nf][q], COEF, -COEF));
    }

    // Quad reduce (4 lanes sharing a row), then cross-warpN via smem
    #pragma unroll
    for (int s = 0; s < 8; s++) {
        float v = rowsum[s];
        v += __shfl_xor_sync(0xffffffffu, v, 1);
        v += __shfl_xor_sync(0xffffffffu, v, 2);
        rowsum[s] = v;
    }
    __syncthreads();                              // all epilogues done before red reuse
    float* red = (float*)(smem + SR);
    if ((lane & 3) == 0) {
        #pragma unroll
        for (int s = 0; s < 8; s++) {
            int row = warpM * 64 + (s >> 1) * 16 + (s & 1) * 8 + (lane >> 2);
            red[warpN * 256 + row] = rowsum[s];
        }
    }
    __syncthreads();
    if (tid < 256) {
        float s = red[tid] + red[256 + tid] + red[512 + tid] + red[768 + tid];
        g_partial[split * B_ROWS + mgrp * 256 + tid] = s;
    }
}

// ---------------------------------------------------------------------------
// Kernel 3a: per-sample loss (parallel gathers). Grid 256 x 256 thr.
// ---------------------------------------------------------------------------
__global__ void kpick(const float* __restrict__ feats,
                      const void* __restrict__ indexes,
                      const void* __restrict__ labels) {
    __shared__ int s64i, s64l;
    int tid = threadIdx.x, lane = tid & 31, w = tid >> 5;
    if (tid == 0) { s64i = sniff_is64(indexes, B_ROWS); s64l = sniff_is64(labels, NFEAT); }
    __syncthreads();
    int b = blockIdx.x * 8 + w;

    float s = (lane < NSPLIT) ? g_partial[lane * B_ROWS + b] : 0.f;
    #pragma unroll
    for (int o = 16; o; o >>= 1) s += __shfl_xor_sync(0xffffffffu, s, o);
    s -= 96.0f * ex2f(-COEF);                    // exact pad-row correction

    long long ix = load_index(indexes, b, s64i);
    if (ix < 0) ix = 0; if (ix >= NFEAT) ix = NFEAT - 1;
    long long tgt = load_index(labels, (int)ix, s64l);
    if (tgt < 0) tgt = 0; if (tgt >= NFEAT) tgt = NFEAT - 1;
    const float* fr = feats + (size_t)tgt * DDIM;
    const float* ir = g_inorm + b * DDIM;
    float d = 0.f;
    #pragma unroll
    for (int k = 0; k < 4; k++) d = fmaf(ir[lane + 32 * k], fr[lane + 32 * k], d);
    #pragma unroll
    for (int o = 16; o; o >>= 1) d += __shfl_xor_sync(0xffffffffu, d, o);
    if (lane == 0) g_loss[b] = (20.0f + logf(s)) - 20.0f * d;
}

// ---------------------------------------------------------------------------
// Kernel 3b: deterministic tree sum of the 2048 losses -> mean
// ---------------------------------------------------------------------------
__global__ void kred(float* __restrict__ out) {
    __shared__ float sm[1024];
    int tid = threadIdx.x;
    sm[tid] = g_loss[tid] + g_loss[tid + 1024];
    __syncthreads();
    #pragma unroll
    for (int off = 512; off > 0; off >>= 1) {
        if (tid < off) sm[tid] += sm[tid + off];
        __syncthreads();
    }
    if (tid == 0) out[0] = sm[0] * (1.0f / (float)B_ROWS);
}

// ---------------------------------------------------------------------------
extern "C" void kernel_launch(void* const* d_in, const int* in_sizes, int n_in,
                              void* d_out, int out_size) {
    const float* inputs = nullptr; const void* indexes = nullptr;
    const void* labels = nullptr;  const float* feats = nullptr;
    for (int i = 0; i < n_in; i++) {
        switch (in_sizes[i]) {
            case B_ROWS * DDIM: inputs = (const float*)d_in[i]; break;
            case B_ROWS:        indexes = d_in[i];              break;
            case NFEAT:         labels = d_in[i];               break;
            case NFEAT * DDIM:  feats = (const float*)d_in[i];  break;
        }
    }
    cudaFuncSetAttribute(kmma, cudaFuncAttributeMaxDynamicSharedMemorySize, 135168);

    kprep<<<NORM_BLKS + CVT_BLKS, 256>>>(inputs, feats);
    kmma<<<dim3(NSPLIT, MGRPS), 512, 135168>>>();
    kpick<<<B_ROWS / 8, 256>>>(feats, indexes, labels);
    kred<<<1, 1024>>>((float*)d_out);
}

// round 15
// speedup vs baseline: 1.0374x; 1.0374x over previous
#include <cuda_runtime.h>
#include <cuda_bf16.h>
#include <math.h>
#include <stdint.h>

// Problem constants
#define B_ROWS   2048
#define DDIM     128
#define NFEAT    100000
#define NSPLIT   18
#define NTILE    782            // ceil(100000/128)
#define NFPAD    (NTILE * 128)  // 100096
#define MGRPS    16             // 16 * 128 = 2048 rows
#define COEF     28.85390081777927f

#define NORM_BLKS 1024                        // 2 rows per block
#define CVT_BLKS  ((NFPAD * DDIM) / (256 * 8))  // 6256

// Scratch (device globals; no allocation allowed)
__device__ float          g_inorm[B_ROWS * DDIM];
__device__ __nv_bfloat16  g_abf[B_ROWS * DDIM];
__device__ __nv_bfloat16  g_fbf[NFPAD * DDIM];
__device__ float          g_partial[NSPLIT * B_ROWS];
__device__ float          g_loss[B_ROWS];

__device__ __forceinline__ float ex2f(float x) {
    float y; asm("ex2.approx.f32 %0, %1;" : "=f"(y) : "f"(x)); return y;
}
__device__ __forceinline__ uint32_t smem_u32(const void* p) {
    uint32_t a;
    asm("{ .reg .u64 t; cvta.to.shared.u64 t, %1; cvt.u32.u64 %0, t; }" : "=r"(a) : "l"(p));
    return a;
}
#define LDSM4(r, addr) \
    asm volatile("ldmatrix.sync.aligned.m8n8.x4.shared.b16 {%0,%1,%2,%3}, [%4];" \
        : "=r"((r)[0]), "=r"((r)[1]), "=r"((r)[2]), "=r"((r)[3]) : "r"(addr))
#define MMA16816(c, a, b0, b1) \
    asm volatile("mma.sync.aligned.m16n8k16.row.col.f32.bf16.bf16.f32 " \
        "{%0,%1,%2,%3},{%4,%5,%6,%7},{%8,%9},{%0,%1,%2,%3};" \
        : "+f"((c)[0]), "+f"((c)[1]), "+f"((c)[2]), "+f"((c)[3]) \
        : "r"((a)[0]), "r"((a)[1]), "r"((a)[2]), "r"((a)[3]), "r"(b0), "r"(b1))
#define CP_ASYNC16(dst, src) \
    asm volatile("cp.async.cg.shared.global [%0], [%1], 16;" :: "r"(dst), "l"(src))
#define CP_COMMIT() asm volatile("cp.async.commit_group;" ::: "memory")
#define CP_WAIT0()  asm volatile("cp.async.wait_group 0;" ::: "memory")

// int dtype handling (proven in R5)
__device__ __forceinline__ long long load_index(const void* p, int i, int is64) {
    if (is64) return ((const long long*)p)[i];
    return (long long)((const int*)p)[i];
}
__device__ __forceinline__ int sniff_is64(const void* p, int nelem) {
    const int* w = (const int*)p;
    int half = nelem / 2, stride = half / 32, allzero = 1;
    #pragma unroll
    for (int i = 0; i < 32; i++) if (w[2 * (i * stride) + 1] != 0) allzero = 0;
    return allzero;
}

// ---------------------------------------------------------------------------
// Kernel 1 (fused): normalize input rows + convert features to padded bf16
// ---------------------------------------------------------------------------
__global__ void kprep(const float* __restrict__ in, const float* __restrict__ feats) {
    int tid = threadIdx.x;
    if (blockIdx.x < NORM_BLKS) {
        __shared__ float ws[2][4];
        int half = tid >> 7;
        int t = tid & 127;
        int row = blockIdx.x * 2 + half;
        float v = in[row * DDIM + t];
        float ss = v * v;
        #pragma unroll
        for (int o = 16; o; o >>= 1) ss += __shfl_xor_sync(0xffffffffu, ss, o);
        if ((t & 31) == 0) ws[half][t >> 5] = ss;
        __syncthreads();
        float inv = 1.0f / fmaxf(sqrtf(ws[half][0] + ws[half][1] + ws[half][2] + ws[half][3]), 1e-12f);
        float nv = v * inv;
        g_inorm[row * DDIM + t] = nv;
        g_abf[row * DDIM + t] = __float2bfloat16_rn(nv);
    } else {
        long long base = ((long long)(blockIdx.x - NORM_BLKS) * 256 + tid) * 8;
        __nv_bfloat162 o[4];
        if (base < (long long)NFEAT * DDIM) {
            float4 v0 = *(const float4*)(feats + base);
            float4 v1 = *(const float4*)(feats + base + 4);
            o[0] = __floats2bfloat162_rn(v0.x, v0.y);
            o[1] = __floats2bfloat162_rn(v0.z, v0.w);
            o[2] = __floats2bfloat162_rn(v1.x, v1.y);
            o[3] = __floats2bfloat162_rn(v1.z, v1.w);
        } else {
            o[0] = o[1] = o[2] = o[3] = __floats2bfloat162_rn(0.f, 0.f);
        }
        *(uint4*)(g_fbf + base) = *(uint4*)o;
    }
}

// ---------------------------------------------------------------------------
// Kernel 2: bf16 mma.sync GEMM + exp-sum epilogue.
// 256 threads (8 warps, 2M x 4N), CTA tile M=128, N=128, K=128; 2 CTAs/SM.
// A resident (32KB); B double-buffered cp.async (2x32KB); smem ~100KB.
// R12-proven ordering: issue -> MMA -> epilogue -> wait -> sync.
// Independent per-CTA barriers let the co-resident CTA fill MUFU/barrier tails.
// ---------------------------------------------------------------------------
__global__ void __launch_bounds__(256, 2)
kmma() {
    extern __shared__ char smem[];
    const int SA = 0, SB = 32768, SR = 98304;    // A 32K | B 2x32K | red 2K
    uint32_t sb = smem_u32(smem);
    int tid = threadIdx.x, wid = tid >> 5, lane = tid & 31;
    int warpM = wid >> 2, warpN = wid & 3;       // 2 x 4
    int split = blockIdx.x, mgrp = blockIdx.y;

    // B cp.async addressing: 8 chunks/thread/tile (base ptr + 32-bit offsets)
    uint32_t boff[8], sdst[8];
    #pragma unroll
    for (int i = 0; i < 8; i++) {
        int ch = i * 256 + tid;
        int r = ch >> 4, c = ch & 15;
        boff[i] = (uint32_t)((r * DDIM + c * 8) * 2);
        sdst[i] = sb + SB + r * 256 + ((c ^ (r & 7)) << 4);
    }
    const char* gbase = (const char*)(g_fbf + (size_t)split * 128 * DDIM);
    const size_t gstep = (size_t)NSPLIT * 128 * DDIM * sizeof(__nv_bfloat16);

    // Issue B tile 0 -> buf 0 (in flight during A load)
    #pragma unroll
    for (int i = 0; i < 8; i++) CP_ASYNC16(sdst[i], gbase + boff[i]);
    CP_COMMIT();
    gbase += gstep;

    // Load A tile: 128 rows x 16 chunks (swizzled), 8 chunks/thread
    #pragma unroll
    for (int i = 0; i < 8; i++) {
        int ch = i * 256 + tid;
        int r = ch >> 4, c = ch & 15;
        uint4 v = *(const uint4*)(g_abf + ((size_t)(mgrp * 128 + r)) * DDIM + c * 8);
        *(uint4*)(smem + SA + r * 256 + ((c ^ (r & 7)) << 4)) = v;
    }
    CP_WAIT0();
    __syncthreads();

    // ldmatrix per-thread address precompute
    int m_in16 = lane & 15, cselA = lane >> 4;
    uint32_t baseA[4]; int a7[4];
    #pragma unroll
    for (int mf = 0; mf < 4; mf++) {
        int row = warpM * 64 + mf * 16 + m_in16;
        baseA[mf] = sb + SA + row * 256;
        a7[mf] = row & 7;
    }
    int n_in16 = ((lane >> 4) << 3) | (lane & 7);
    int cselB = (lane >> 3) & 1;
    uint32_t baseB[2]; int b7[2];
    #pragma unroll
    for (int p = 0; p < 2; p++) {
        int row = warpN * 32 + p * 16 + n_in16;
        baseB[p] = sb + SB + row * 256;
        b7[p] = row & 7;
    }

    float rowsum[8];
    #pragma unroll
    for (int s = 0; s < 8; s++) rowsum[s] = 0.f;

    int j = 0;
    for (int t = split; t < NTILE; t += NSPLIT, j++) {
        int has_next = (t + NSPLIT < NTILE);
        if (has_next) {
            uint32_t dx = (uint32_t)(((j + 1) & 1) * 32768);
            #pragma unroll
            for (int i = 0; i < 8; i++) CP_ASYNC16(sdst[i] + dx, gbase + boff[i]);
            CP_COMMIT();
            gbase += gstep;
        }

        uint32_t bufoff = (uint32_t)((j & 1) * 32768);
        float acc[4][4][4];
        #pragma unroll
        for (int mf = 0; mf < 4; mf++)
            #pragma unroll
            for (int nf = 0; nf < 4; nf++)
                #pragma unroll
                for (int q = 0; q < 4; q++) acc[mf][nf][q] = 0.f;

        #pragma unroll
        for (int ks = 0; ks < 8; ks++) {
            uint32_t a[4][4], bb[2][4];
            #pragma unroll
            for (int mf = 0; mf < 4; mf++)
                LDSM4(a[mf], baseA[mf] + (((2 * ks + cselA) ^ a7[mf]) << 4));
            #pragma unroll
            for (int p = 0; p < 2; p++)
                LDSM4(bb[p], baseB[p] + bufoff + (((2 * ks + cselB) ^ b7[p]) << 4));
            #pragma unroll
            for (int mf = 0; mf < 4; mf++)
                #pragma unroll
                for (int nf = 0; nf < 4; nf++)
                    MMA16816(acc[mf][nf], a[mf], bb[nf >> 1][(nf & 1) * 2],
                             bb[nf >> 1][(nf & 1) * 2 + 1]);
        }

        // Epilogue first (R12 ordering): overlaps the in-flight cp.async
        #pragma unroll
        for (int mf = 0; mf < 4; mf++)
            #pragma unroll
            for (int nf = 0; nf < 4; nf++)
                #pragma unroll
                for (int q = 0; q < 4; q++)
                    rowsum[mf * 2 + (q >> 1)] += ex2f(fmaf(acc[mf][nf][q], COEF, -COEF));

        if (has_next) CP_WAIT0();
        __syncthreads();
    }

    // Quad reduce (4 lanes sharing a row), then cross-warpN via smem
    #pragma unroll
    for (int s = 0; s < 8; s++) {
        float v = rowsum[s];
        v += __shfl_xor_sync(0xffffffffu, v, 1);
        v += __shfl_xor_sync(0xffffffffu, v, 2);
        rowsum[s] = v;
    }
    float* red = (float*)(smem + SR);             // 512 floats, dedicated region
    if ((lane & 3) == 0) {
        #pragma unroll
        for (int s = 0; s < 8; s++) {
            int row = warpM * 64 + (s >> 1) * 16 + (s & 1) * 8 + (lane >> 2);
            red[warpN * 128 + row] = rowsum[s];
        }
    }
    __syncthreads();
    if (tid < 128) {
        float s = red[tid] + red[128 + tid] + red[256 + tid] + red[384 + tid];
        g_partial[split * B_ROWS + mgrp * 128 + tid] = s;
    }
}

// ---------------------------------------------------------------------------
// Kernel 3a: per-sample loss (parallel gathers). Grid 256 x 256 thr.
// ---------------------------------------------------------------------------
__global__ void kpick(const float* __restrict__ feats,
                      const void* __restrict__ indexes,
                      const void* __restrict__ labels) {
    __shared__ int s64i, s64l;
    int tid = threadIdx.x, lane = tid & 31, w = tid >> 5;
    if (tid == 0) { s64i = sniff_is64(indexes, B_ROWS); s64l = sniff_is64(labels, NFEAT); }
    __syncthreads();
    int b = blockIdx.x * 8 + w;

    float s = (lane < NSPLIT) ? g_partial[lane * B_ROWS + b] : 0.f;
    #pragma unroll
    for (int o = 16; o; o >>= 1) s += __shfl_xor_sync(0xffffffffu, s, o);
    s -= 96.0f * ex2f(-COEF);                    // exact pad-row correction

    long long ix = load_index(indexes, b, s64i);
    if (ix < 0) ix = 0; if (ix >= NFEAT) ix = NFEAT - 1;
    long long tgt = load_index(labels, (int)ix, s64l);
    if (tgt < 0) tgt = 0; if (tgt >= NFEAT) tgt = NFEAT - 1;
    const float* fr = feats + (size_t)tgt * DDIM;
    const float* ir = g_inorm + b * DDIM;
    float d = 0.f;
    #pragma unroll
    for (int k = 0; k < 4; k++) d = fmaf(ir[lane + 32 * k], fr[lane + 32 * k], d);
    #pragma unroll
    for (int o = 16; o; o >>= 1) d += __shfl_xor_sync(0xffffffffu, d, o);
    if (lane == 0) g_loss[b] = (20.0f + logf(s)) - 20.0f * d;
}

// ---------------------------------------------------------------------------
// Kernel 3b: deterministic tree sum of the 2048 losses -> mean
// ---------------------------------------------------------------------------
__global__ void kred(float* __restrict__ out) {
    __shared__ float sm[1024];
    int tid = threadIdx.x;
    sm[tid] = g_loss[tid] + g_loss[tid + 1024];
    __syncthreads();
    #pragma unroll
    for (int off = 512; off > 0; off >>= 1) {
        if (tid < off) sm[tid] += sm[tid + off];
        __syncthreads();
    }
    if (tid == 0) out[0] = sm[0] * (1.0f / (float)B_ROWS);
}

// ---------------------------------------------------------------------------
extern "C" void kernel_launch(void* const* d_in, const int* in_sizes, int n_in,
                              void* d_out, int out_size) {
    const float* inputs = nullptr; const void* indexes = nullptr;
    const void* labels = nullptr;  const float* feats = nullptr;
    for (int i = 0; i < n_in; i++) {
        switch (in_sizes[i]) {
            case B_ROWS * DDIM: inputs = (const float*)d_in[i]; break;
            case B_ROWS:        indexes = d_in[i];              break;
            case NFEAT:         labels = d_in[i];               break;
            case NFEAT * DDIM:  feats = (const float*)d_in[i];  break;
        }
    }
    cudaFuncSetAttribute(kmma, cudaFuncAttributeMaxDynamicSharedMemorySize, 100352);

    kprep<<<NORM_BLKS + CVT_BLKS, 256>>>(inputs, feats);
    kmma<<<dim3(NSPLIT, MGRPS), 256, 100352>>>();
    kpick<<<B_ROWS / 8, 256>>>(feats, indexes, labels);
    kred<<<1, 1024>>>((float*)d_out);
}

// round 17
// speedup vs baseline: 1.0388x; 1.0014x over previous
#include <cuda_runtime.h>
#include <cuda_bf16.h>
#include <cuda_fp16.h>
#include <math.h>
#include <stdint.h>

// Problem constants
#define B_ROWS   2048
#define DDIM     128
#define NFEAT    100000
#define NSPLIT   18
#define NTILE    782            // ceil(100000/128)
#define NFPAD    (NTILE * 128)  // 100096
#define MGRPS    16             // 16 * 128 = 2048 rows
#define COEF     28.85390081777927f
#define SHIFTF   14.0f
#define SHIFT_LN2 9.704060527839234f      // 14 * ln(2)
#define PAD_TERM 0.00006103515625f        // 2^-14 (exact)

#define NORM_BLKS 1024                        // 2 rows per block
#define CVT_BLKS  ((NFPAD * DDIM) / (256 * 8))  // 6256

// Scratch (device globals; no allocation allowed)
__device__ float          g_inorm[B_ROWS * DDIM];
__device__ __nv_bfloat16  g_abf[B_ROWS * DDIM];
__device__ __nv_bfloat16  g_fbf[NFPAD * DDIM];
__device__ float          g_partial[NSPLIT * B_ROWS];
__device__ float          g_loss[B_ROWS];

__device__ __forceinline__ float ex2f(float x) {
    float y; asm("ex2.approx.f32 %0, %1;" : "=f"(y) : "f"(x)); return y;
}
__device__ __forceinline__ uint32_t smem_u32(const void* p) {
    uint32_t a;
    asm("{ .reg .u64 t; cvta.to.shared.u64 t, %1; cvt.u32.u64 %0, t; }" : "=r"(a) : "l"(p));
    return a;
}
#define LDSM4(r, addr) \
    asm volatile("ldmatrix.sync.aligned.m8n8.x4.shared.b16 {%0,%1,%2,%3}, [%4];" \
        : "=r"((r)[0]), "=r"((r)[1]), "=r"((r)[2]), "=r"((r)[3]) : "r"(addr))
#define MMA16816(c, a, b0, b1) \
    asm volatile("mma.sync.aligned.m16n8k16.row.col.f32.bf16.bf16.f32 " \
        "{%0,%1,%2,%3},{%4,%5,%6,%7},{%8,%9},{%0,%1,%2,%3};" \
        : "+f"((c)[0]), "+f"((c)[1]), "+f"((c)[2]), "+f"((c)[3]) \
        : "r"((a)[0]), "r"((a)[1]), "r"((a)[2]), "r"((a)[3]), "r"(b0), "r"(b1))
#define CP_ASYNC16(dst, src) \
    asm volatile("cp.async.cg.shared.global [%0], [%1], 16;" :: "r"(dst), "l"(src))
#define CP_COMMIT() asm volatile("cp.async.commit_group;" ::: "memory")
#define CP_WAIT0()  asm volatile("cp.async.wait_group 0;" ::: "memory")

// int dtype handling (proven in R5)
__device__ __forceinline__ long long load_index(const void* p, int i, int is64) {
    if (is64) return ((const long long*)p)[i];
    return (long long)((const int*)p)[i];
}
__device__ __forceinline__ int sniff_is64(const void* p, int nelem) {
    const int* w = (const int*)p;
    int half = nelem / 2, stride = half / 32, allzero = 1;
    #pragma unroll
    for (int i = 0; i < 32; i++) if (w[2 * (i * stride) + 1] != 0) allzero = 0;
    return allzero;
}

// ---------------------------------------------------------------------------
// Kernel 1 (fused): normalize input rows + convert features to padded bf16
// ---------------------------------------------------------------------------
__global__ void kprep(const float* __restrict__ in, const float* __restrict__ feats) {
    int tid = threadIdx.x;
    if (blockIdx.x < NORM_BLKS) {
        __shared__ float ws[2][4];
        int half = tid >> 7;
        int t = tid & 127;
        int row = blockIdx.x * 2 + half;
        float v = in[row * DDIM + t];
        float ss = v * v;
        #pragma unroll
        for (int o = 16; o; o >>= 1) ss += __shfl_xor_sync(0xffffffffu, ss, o);
        if ((t & 31) == 0) ws[half][t >> 5] = ss;
        __syncthreads();
        float inv = 1.0f / fmaxf(sqrtf(ws[half][0] + ws[half][1] + ws[half][2] + ws[half][3]), 1e-12f);
        float nv = v * inv;
        g_inorm[row * DDIM + t] = nv;
        g_abf[row * DDIM + t] = __float2bfloat16_rn(nv);
    } else {
        long long base = ((long long)(blockIdx.x - NORM_BLKS) * 256 + tid) * 8;
        __nv_bfloat162 o[4];
        if (base < (long long)NFEAT * DDIM) {
            float4 v0 = *(const float4*)(feats + base);
            float4 v1 = *(const float4*)(feats + base + 4);
            o[0] = __floats2bfloat162_rn(v0.x, v0.y);
            o[1] = __floats2bfloat162_rn(v0.z, v0.w);
            o[2] = __floats2bfloat162_rn(v1.x, v1.y);
            o[3] = __floats2bfloat162_rn(v1.z, v1.w);
        } else {
            o[0] = o[1] = o[2] = o[3] = __floats2bfloat162_rn(0.f, 0.f);
        }
        *(uint4*)(g_fbf + base) = *(uint4*)o;
    }
}

// ---------------------------------------------------------------------------
// Kernel 2: bf16 mma.sync GEMM + half2-ex2 exp-sum epilogue.
// 256 threads (8 warps, 2M x 4N), CTA tile M=128, N=128, K=128; 2 CTAs/SM.
// Epilogue packs logit pairs into half2 and uses ex2.approx.f16x2 (one MUFU
// op per 2 elements), halving the MUFU load that the R15 model says binds.
// Shift 2^-14: overflow impossible (|dot|<=1), underflow negligible.
// ---------------------------------------------------------------------------
__global__ void __launch_bounds__(256, 2)
kmma() {
    extern __shared__ char smem[];
    const int SA = 0, SB = 32768, SR = 98304;    // A 32K | B 2x32K | red 2K
    uint32_t sb = smem_u32(smem);
    int tid = threadIdx.x, wid = tid >> 5, lane = tid & 31;
    int warpM = wid >> 2, warpN = wid & 3;       // 2 x 4
    int split = blockIdx.x, mgrp = blockIdx.y;

    // B cp.async addressing: 8 chunks/thread/tile (base ptr + 32-bit offsets)
    uint32_t boff[8], sdst[8];
    #pragma unroll
    for (int i = 0; i < 8; i++) {
        int ch = i * 256 + tid;
        int r = ch >> 4, c = ch & 15;
        boff[i] = (uint32_t)((r * DDIM + c * 8) * 2);
        sdst[i] = sb + SB + r * 256 + ((c ^ (r & 7)) << 4);
    }
    const char* gbase = (const char*)(g_fbf + (size_t)split * 128 * DDIM);
    const size_t gstep = (size_t)NSPLIT * 128 * DDIM * sizeof(__nv_bfloat16);

    // Issue B tile 0 -> buf 0 (in flight during A load)
    #pragma unroll
    for (int i = 0; i < 8; i++) CP_ASYNC16(sdst[i], gbase + boff[i]);
    CP_COMMIT();
    gbase += gstep;

    // Load A tile: 128 rows x 16 chunks (swizzled), 8 chunks/thread
    #pragma unroll
    for (int i = 0; i < 8; i++) {
        int ch = i * 256 + tid;
        int r = ch >> 4, c = ch & 15;
        uint4 v = *(const uint4*)(g_abf + ((size_t)(mgrp * 128 + r)) * DDIM + c * 8);
        *(uint4*)(smem + SA + r * 256 + ((c ^ (r & 7)) << 4)) = v;
    }
    CP_WAIT0();
    __syncthreads();

    // ldmatrix per-thread address precompute
    int m_in16 = lane & 15, cselA = lane >> 4;
    uint32_t baseA[4]; int a7[4];
    #pragma unroll
    for (int mf = 0; mf < 4; mf++) {
        int row = warpM * 64 + mf * 16 + m_in16;
        baseA[mf] = sb + SA + row * 256;
        a7[mf] = row & 7;
    }
    int n_in16 = ((lane >> 4) << 3) | (lane & 7);
    int cselB = (lane >> 3) & 1;
    uint32_t baseB[2]; int b7[2];
    #pragma unroll
    for (int p = 0; p < 2; p++) {
        int row = warpN * 32 + p * 16 + n_in16;
        baseB[p] = sb + SB + row * 256;
        b7[p] = row & 7;
    }

    float rowsum[8];
    #pragma unroll
    for (int s = 0; s < 8; s++) rowsum[s] = 0.f;

    int j = 0;
    for (int t = split; t < NTILE; t += NSPLIT, j++) {
        int has_next = (t + NSPLIT < NTILE);
        if (has_next) {
            uint32_t dx = (uint32_t)(((j + 1) & 1) * 32768);
            #pragma unroll
            for (int i = 0; i < 8; i++) CP_ASYNC16(sdst[i] + dx, gbase + boff[i]);
            CP_COMMIT();
            gbase += gstep;
        }

        uint32_t bufoff = (uint32_t)((j & 1) * 32768);
        float acc[4][4][4];
        #pragma unroll
        for (int mf = 0; mf < 4; mf++)
            #pragma unroll
            for (int nf = 0; nf < 4; nf++)
                #pragma unroll
                for (int q = 0; q < 4; q++) acc[mf][nf][q] = 0.f;

        #pragma unroll
        for (int ks = 0; ks < 8; ks++) {
            uint32_t a[4][4], bb[2][4];
            #pragma unroll
            for (int mf = 0; mf < 4; mf++)
                LDSM4(a[mf], baseA[mf] + (((2 * ks + cselA) ^ a7[mf]) << 4));
            #pragma unroll
            for (int p = 0; p < 2; p++)
                LDSM4(bb[p], baseB[p] + bufoff + (((2 * ks + cselB) ^ b7[p]) << 4));
            #pragma unroll
            for (int mf = 0; mf < 4; mf++)
                #pragma unroll
                for (int nf = 0; nf < 4; nf++)
                    MMA16816(acc[mf][nf], a[mf], bb[nf >> 1][(nf & 1) * 2],
                             bb[nf >> 1][(nf & 1) * 2 + 1]);
        }

        // Epilogue (R12 ordering: before wait/sync). half2 ex2: per pair,
        // 2 fp32 FFMA (exact scale) -> pack -> one MUFU h2exp2 -> HADD2.
        // q0,q1 share a row; q2,q3 share the other -> clean pairing.
        #pragma unroll
        for (int mf = 0; mf < 4; mf++) {
            __half2 h0 = __float2half2_rn(0.f);
            __half2 h1 = __float2half2_rn(0.f);
            #pragma unroll
            for (int nf = 0; nf < 4; nf++) {
                float x0 = fmaf(acc[mf][nf][0], COEF, -SHIFTF);
                float x1 = fmaf(acc[mf][nf][1], COEF, -SHIFTF);
                float x2 = fmaf(acc[mf][nf][2], COEF, -SHIFTF);
                float x3 = fmaf(acc[mf][nf][3], COEF, -SHIFTF);
                h0 = __hadd2(h0, h2exp2(__floats2half2_rn(x0, x1)));
                h1 = __hadd2(h1, h2exp2(__floats2half2_rn(x2, x3)));
            }
            rowsum[mf * 2 + 0] += __low2float(h0) + __high2float(h0);
            rowsum[mf * 2 + 1] += __low2float(h1) + __high2float(h1);
        }

        if (has_next) CP_WAIT0();
        __syncthreads();
    }

    // Quad reduce (4 lanes sharing a row), then cross-warpN via smem
    #pragma unroll
    for (int s = 0; s < 8; s++) {
        float v = rowsum[s];
        v += __shfl_xor_sync(0xffffffffu, v, 1);
        v += __shfl_xor_sync(0xffffffffu, v, 2);
        rowsum[s] = v;
    }
    float* red = (float*)(smem + SR);             // 512 floats, dedicated region
    if ((lane & 3) == 0) {
        #pragma unroll
        for (int s = 0; s < 8; s++) {
            int row = warpM * 64 + (s >> 1) * 16 + (s & 1) * 8 + (lane >> 2);
            red[warpN * 128 + row] = rowsum[s];
        }
    }
    __syncthreads();
    if (tid < 128) {
        float s = red[tid] + red[128 + tid] + red[256 + tid] + red[384 + tid];
        g_partial[split * B_ROWS + mgrp * 128 + tid] = s;
    }
}

// ---------------------------------------------------------------------------
// Kernel 3a: per-sample loss. logz = 14*ln2 + ln(S); pad term 2^-14 exact.
// ---------------------------------------------------------------------------
__global__ void kpick(const float* __restrict__ feats,
                      const void* __restrict__ indexes,
                      const void* __restrict__ labels) {
    __shared__ int s64i, s64l;
    int tid = threadIdx.x, lane = tid & 31, w = tid >> 5;
    if (tid == 0) { s64i = sniff_is64(indexes, B_ROWS); s64l = sniff_is64(labels, NFEAT); }
    __syncthreads();
    int b = blockIdx.x * 8 + w;

    float s = (lane < NSPLIT) ? g_partial[lane * B_ROWS + b] : 0.f;
    #pragma unroll
    for (int o = 16; o; o >>= 1) s += __shfl_xor_sync(0xffffffffu, s, o);
    s -= 96.0f * PAD_TERM;                       // exact pad-row correction

    long long ix = load_index(indexes, b, s64i);
    if (ix < 0) ix = 0; if (ix >= NFEAT) ix = NFEAT - 1;
    long long tgt = load_index(labels, (int)ix, s64l);
    if (tgt < 0) tgt = 0; if (tgt >= NFEAT) tgt = NFEAT - 1;
    const float* fr = feats + (size_t)tgt * DDIM;
    const float* ir = g_inorm + b * DDIM;
    float d = 0.f;
    #pragma unroll
    for (int k = 0; k < 4; k++) d = fmaf(ir[lane + 32 * k], fr[lane + 32 * k], d);
    #pragma unroll
    for (int o = 16; o; o >>= 1) d += __shfl_xor_sync(0xffffffffu, d, o);
    if (lane == 0) g_loss[b] = (SHIFT_LN2 + logf(s)) - 20.0f * d;
}

// ---------------------------------------------------------------------------
// Kernel 3b: deterministic tree sum of the 2048 losses -> mean
// ---------------------------------------------------------------------------
__global__ void kred(float* __restrict__ out) {
    __shared__ float sm[1024];
    int tid = threadIdx.x;
    sm[tid] = g_loss[tid] + g_loss[tid + 1024];
    __syncthreads();
    #pragma unroll
    for (int off = 512; off > 0; off >>= 1) {
        if (tid < off) sm[tid] += sm[tid + off];
        __syncthreads();
    }
    if (tid == 0) out[0] = sm[0] * (1.0f / (float)B_ROWS);
}

// ---------------------------------------------------------------------------
extern "C" void kernel_launch(void* const* d_in, const int* in_sizes, int n_in,
                              void* d_out, int out_size) {
    const float* inputs = nullptr; const void* indexes = nullptr;
    const void* labels = nullptr;  const float* feats = nullptr;
    for (int i = 0; i < n_in; i++) {
        switch (in_sizes[i]) {
            case B_ROWS * DDIM: inputs = (const float*)d_in[i]; break;
            case B_ROWS:        indexes = d_in[i];              break;
            case NFEAT:         labels = d_in[i];               break;
            case NFEAT * DDIM:  feats = (const float*)d_in[i];  break;
        }
    }
    cudaFuncSetAttribute(kmma, cudaFuncAttributeMaxDynamicSharedMemorySize, 100352);

    kprep<<<NORM_BLKS + CVT_BLKS, 256>>>(inputs, feats);
    kmma<<<dim3(NSPLIT, MGRPS), 256, 100352>>>();
    kpick<<<B_ROWS / 8, 256>>>(feats, indexes, labels);
    kred<<<1, 1024>>>((float*)d_out);
}